// round 2
// baseline (speedup 1.0000x reference)
#include <cuda_runtime.h>

#define B_ 4
#define T_ 128
#define N_ 512
#define D_ 32
#define JN_ 16384       // (B*T)*D
#define EMB_ 10

// ---------------- scratch (device globals; no allocations allowed) ----------
__device__ float g_buf0[N_ * JN_];       // layout (n, bt, c), bt = b*T+t
__device__ float g_buf1[N_ * JN_];
__device__ float g_xg[2 * N_ * JN_];     // aggregated supports k=1,2
__device__ float g_S2[N_ * N_];
__device__ float g_W[3 * N_ * 3 * D_ * D_];   // per-layer per-node (k,c,o)
__device__ float g_bias[3 * N_ * D_];

// ---------------- transpose x (bt,n,c) -> (n,bt,c) --------------------------
__global__ void k_transpose(const float* __restrict__ x) {
    int n = blockIdx.x, bt0 = blockIdx.y * 64, tid = threadIdx.x;
#pragma unroll
    for (int j = 0; j < 8; j++) {
        int idx = j * 256 + tid;
        int r = idx >> 5, c = idx & 31;
        g_buf0[n * JN_ + (bt0 + r) * D_ + c] =
            x[(bt0 + r) * (N_ * D_) + n * D_ + c];
    }
}

// ---------------- S2 = 2*adj@adj - I ----------------------------------------
__global__ void k_s2(const float* __restrict__ A) {
    __shared__ float As[32][33], Bs[32][33];
    int by = blockIdx.y, bx = blockIdx.x, tid = threadIdx.x;
    int ty = tid >> 5, tx = tid & 31;
    float acc[4] = {0.f, 0.f, 0.f, 0.f};
    for (int m0 = 0; m0 < N_; m0 += 32) {
#pragma unroll
        for (int i = 0; i < 4; i++) {
            int r = ty + i * 8;
            As[r][tx] = A[(by * 32 + r) * N_ + m0 + tx];
            Bs[r][tx] = A[(m0 + r) * N_ + bx * 32 + tx];
        }
        __syncthreads();
#pragma unroll
        for (int m = 0; m < 32; m++) {
            float b = Bs[m][tx];
#pragma unroll
            for (int i = 0; i < 4; i++) acc[i] += As[ty + i * 8][m] * b;
        }
        __syncthreads();
    }
#pragma unroll
    for (int i = 0; i < 4; i++) {
        int r = by * 32 + ty + i * 8, c = bx * 32 + tx;
        g_S2[r * N_ + c] = 2.f * acc[i] - (r == c ? 1.f : 0.f);
    }
}

// ---------------- per-node GCN weights: W[n,k,c,o] = sum_e E[n,e] gw[e,k,c,o]
__global__ void k_wn(const float* __restrict__ E, const float* __restrict__ gw,
                     const float* __restrict__ gb) {
    int n = blockIdx.x, L = blockIdx.y, tid = threadIdx.x;
    float Er[EMB_];
#pragma unroll
    for (int e = 0; e < EMB_; e++) Er[e] = E[n * EMB_ + e];
    const float* g0 = gw + L * (EMB_ * 3072);
    float* wout = g_W + (L * N_ + n) * 3072;
    for (int idx = tid; idx < 3072; idx += 256) {
        float a = 0.f;
#pragma unroll
        for (int e = 0; e < EMB_; e++) a += Er[e] * g0[e * 3072 + idx];
        wout[idx] = a;
    }
    if (tid < 32) {
        const float* b0 = gb + L * (EMB_ * 32);
        float a = 0.f;
#pragma unroll
        for (int e = 0; e < EMB_; e++) a += Er[e] * b0[e * 32 + tid];
        g_bias[(L * N_ + n) * 32 + tid] = a;
    }
}

// ---------------- aggregation GEMM: [adj;S2](1024x512) @ H(512x16384) -------
__global__ void k_agg(const float* __restrict__ adj, int inSel) {
    __shared__ float As[16][132];
    __shared__ float Bs[16][132];
    const float* Hin = inSel ? g_buf1 : g_buf0;
    int bx = blockIdx.x, by = blockIdx.y, tid = threadIdx.x;
    const float* Ap = (by < 4) ? (adj + by * 128 * N_) : (g_S2 + (by - 4) * 128 * N_);
    int bn0 = bx * 128;
    int ty = tid >> 4, tx = tid & 15;
    float acc[8][8];
#pragma unroll
    for (int i = 0; i < 8; i++)
#pragma unroll
        for (int j = 0; j < 8; j++) acc[i][j] = 0.f;

    for (int m0 = 0; m0 < N_; m0 += 16) {
#pragma unroll
        for (int q = tid; q < 512; q += 256) {
            int r = q >> 2, c4 = (q & 3) * 4;
            float4 v = *(const float4*)&Ap[r * N_ + m0 + c4];
            As[c4 + 0][r] = v.x; As[c4 + 1][r] = v.y;
            As[c4 + 2][r] = v.z; As[c4 + 3][r] = v.w;
        }
#pragma unroll
        for (int q = tid; q < 512; q += 256) {
            int kk = q >> 5, c4 = (q & 31) * 4;
            *(float4*)&Bs[kk][c4] =
                *(const float4*)&Hin[(m0 + kk) * JN_ + bn0 + c4];
        }
        __syncthreads();
#pragma unroll
        for (int kk = 0; kk < 16; kk++) {
            float ra[8], rb[8];
            *(float4*)&ra[0] = *(const float4*)&As[kk][ty * 8];
            *(float4*)&ra[4] = *(const float4*)&As[kk][ty * 8 + 4];
            *(float4*)&rb[0] = *(const float4*)&Bs[kk][tx * 8];
            *(float4*)&rb[4] = *(const float4*)&Bs[kk][tx * 8 + 4];
#pragma unroll
            for (int i = 0; i < 8; i++)
#pragma unroll
                for (int j = 0; j < 8; j++) acc[i][j] += ra[i] * rb[j];
        }
        __syncthreads();
    }
    int r0 = by * 128 + ty * 8;
#pragma unroll
    for (int i = 0; i < 8; i++) {
        float* o = &g_xg[(r0 + i) * JN_ + bn0 + tx * 8];
        *(float4*)&o[0] = make_float4(acc[i][0], acc[i][1], acc[i][2], acc[i][3]);
        *(float4*)&o[4] = make_float4(acc[i][4], acc[i][5], acc[i][6], acc[i][7]);
    }
}

// ---------------- combine: out[n,bt,o] = sum_kc [H|xg1|xg2] * W[n] + b[n] ---
__global__ void k_combine(int inSel, int L) {
    __shared__ float Xin[64][97];
    __shared__ float Ws[3072];
    __shared__ float bs[32];
    const float* Hin = inSel ? g_buf1 : g_buf0;
    float* Hout = inSel ? g_buf0 : g_buf1;
    int n = blockIdx.x, bt0 = blockIdx.y * 64, tid = threadIdx.x;
    const float* Wl = g_W + (L * N_ + n) * 3072;
    for (int q = tid; q < 3072; q += 256) Ws[q] = Wl[q];
    if (tid < 32) bs[tid] = g_bias[(L * N_ + n) * 32 + tid];
    const float* s0 = Hin + n * JN_ + bt0 * D_;
    const float* s1 = g_xg + n * JN_ + bt0 * D_;
    const float* s2 = g_xg + (N_ + n) * JN_ + bt0 * D_;
#pragma unroll
    for (int q = tid; q < 2048; q += 256) {
        int r = q >> 5, c = q & 31;
        Xin[r][c] = s0[q];
        Xin[r][32 + c] = s1[q];
        Xin[r][64 + c] = s2[q];
    }
    __syncthreads();
    int tx = tid & 7, ty = tid >> 3;
    float a00 = 0, a01 = 0, a02 = 0, a03 = 0, a10 = 0, a11 = 0, a12 = 0, a13 = 0;
    for (int kc = 0; kc < 96; kc++) {
        float4 w = *(const float4*)&Ws[kc * 32 + tx * 4];
        float x0 = Xin[ty * 2][kc], x1 = Xin[ty * 2 + 1][kc];
        a00 += x0 * w.x; a01 += x0 * w.y; a02 += x0 * w.z; a03 += x0 * w.w;
        a10 += x1 * w.x; a11 += x1 * w.y; a12 += x1 * w.z; a13 += x1 * w.w;
    }
    float b0 = bs[tx * 4], b1 = bs[tx * 4 + 1], b2 = bs[tx * 4 + 2], b3 = bs[tx * 4 + 3];
    int bt = bt0 + ty * 2;
    *(float4*)&Hout[n * JN_ + bt * D_ + tx * 4] =
        make_float4(a00 + b0, a01 + b1, a02 + b2, a03 + b3);
    *(float4*)&Hout[n * JN_ + (bt + 1) * D_ + tx * 4] =
        make_float4(a10 + b0, a11 + b1, a12 + b2, a13 + b3);
}

// ---------------- fused TCN: 3 blocks, dilations 1,2,4, per-sequence --------
__global__ void k_tcn(const float* __restrict__ w1, const float* __restrict__ b1,
                      const float* __restrict__ w2, const float* __restrict__ b2,
                      int sel) {
    __shared__ float y0[32][129];
    __shared__ float y1[32][129];
    __shared__ float2 wab[1024];
    __shared__ float wcc[1024];
    __shared__ float bb[32];
    float* seq = (sel ? g_buf1 : g_buf0) + blockIdx.x * 4096;
    int t = threadIdx.x;
#pragma unroll
    for (int j = 0; j < 32; j++) {
        int idx = j * 128 + t;
        y0[idx & 31][idx >> 5] = seq[idx];
    }
    for (int blk = 0; blk < 3; blk++) {
        int dil = 1 << blk;
        __syncthreads();
        const float* ws = w1 + blk * 3072;
        for (int q = t; q < 1024; q += 128) {
            wab[q] = make_float2(ws[q * 3], ws[q * 3 + 1]);
            wcc[q] = ws[q * 3 + 2];
        }
        if (t < 32) bb[t] = b1[blk * 32 + t];
        __syncthreads();
        float acc[32];
#pragma unroll
        for (int o = 0; o < 32; o++) acc[o] = bb[o];
        for (int c = 0; c < 32; c++) {
            float i0 = (t >= 2 * dil) ? y0[c][t - 2 * dil] : 0.f;
            float i1 = (t >= dil) ? y0[c][t - dil] : 0.f;
            float i2 = y0[c][t];
#pragma unroll
            for (int o = 0; o < 32; o++) {
                float2 w = wab[o * 32 + c];
                acc[o] += w.x * i0 + w.y * i1 + wcc[o * 32 + c] * i2;
            }
        }
#pragma unroll
        for (int o = 0; o < 32; o++) y1[o][t] = fmaxf(acc[o], 0.f);
        __syncthreads();
        const float* ws2 = w2 + blk * 3072;
        for (int q = t; q < 1024; q += 128) {
            wab[q] = make_float2(ws2[q * 3], ws2[q * 3 + 1]);
            wcc[q] = ws2[q * 3 + 2];
        }
        if (t < 32) bb[t] = b2[blk * 32 + t];
        __syncthreads();
#pragma unroll
        for (int o = 0; o < 32; o++) acc[o] = bb[o];
        for (int c = 0; c < 32; c++) {
            float i0 = (t >= 2 * dil) ? y1[c][t - 2 * dil] : 0.f;
            float i1 = (t >= dil) ? y1[c][t - dil] : 0.f;
            float i2 = y1[c][t];
#pragma unroll
            for (int o = 0; o < 32; o++) {
                float2 w = wab[o * 32 + c];
                acc[o] += w.x * i0 + w.y * i1 + wcc[o * 32 + c] * i2;
            }
        }
#pragma unroll
        for (int o = 0; o < 32; o++)
            y0[o][t] = fmaxf(fmaxf(acc[o], 0.f) + y0[o][t], 0.f);
    }
    __syncthreads();
#pragma unroll
    for (int j = 0; j < 32; j++) {
        int idx = j * 128 + t;
        seq[idx] = y0[idx & 31][idx >> 5];
    }
}

// ---------------- temporal attention + layernorm, thread = query t ----------
__global__ void k_attn(const float* __restrict__ wq, const float* __restrict__ wk,
                       const float* __restrict__ wv, const float* __restrict__ wo,
                       const float* __restrict__ gga, const float* __restrict__ bba,
                       int sel, float* __restrict__ finalOut) {
    __shared__ float Ks[128][33];
    __shared__ float Vs[128][33];
    __shared__ float Wb[3][1024];
    __shared__ float gs[32], bs2[32];
    float* seq = (sel ? g_buf1 : g_buf0) + blockIdx.x * 4096;
    int t = threadIdx.x;
    for (int q = t; q < 1024; q += 128) {
        Wb[0][q] = wq[q]; Wb[1][q] = wk[q]; Wb[2][q] = wv[q];
    }
    if (t < 32) { gs[t] = gga[t]; bs2[t] = bba[t]; }
    __syncthreads();

    float hrow[32];
#pragma unroll
    for (int o4 = 0; o4 < 8; o4++)
        *(float4*)&hrow[o4 * 4] = *(const float4*)&seq[t * 32 + o4 * 4];

    float qv[32];
#pragma unroll
    for (int o = 0; o < 32; o++) qv[o] = 0.f;
    for (int c = 0; c < 32; c++) {
        float h = hrow[c];
#pragma unroll
        for (int o4 = 0; o4 < 8; o4++) {
            float4 a = *(const float4*)&Wb[0][c * 32 + o4 * 4];
            qv[o4 * 4 + 0] += h * a.x; qv[o4 * 4 + 1] += h * a.y;
            qv[o4 * 4 + 2] += h * a.z; qv[o4 * 4 + 3] += h * a.w;
        }
    }
#pragma unroll
    for (int o = 0; o < 32; o++) qv[o] *= 0.25f;  // 1/sqrt(16)

    float tv[32];
#pragma unroll
    for (int o = 0; o < 32; o++) tv[o] = 0.f;
    for (int c = 0; c < 32; c++) {
        float h = hrow[c];
#pragma unroll
        for (int o4 = 0; o4 < 8; o4++) {
            float4 a = *(const float4*)&Wb[1][c * 32 + o4 * 4];
            tv[o4 * 4 + 0] += h * a.x; tv[o4 * 4 + 1] += h * a.y;
            tv[o4 * 4 + 2] += h * a.z; tv[o4 * 4 + 3] += h * a.w;
        }
    }
#pragma unroll
    for (int o = 0; o < 32; o++) Ks[t][o] = tv[o];
#pragma unroll
    for (int o = 0; o < 32; o++) tv[o] = 0.f;
    for (int c = 0; c < 32; c++) {
        float h = hrow[c];
#pragma unroll
        for (int o4 = 0; o4 < 8; o4++) {
            float4 a = *(const float4*)&Wb[2][c * 32 + o4 * 4];
            tv[o4 * 4 + 0] += h * a.x; tv[o4 * 4 + 1] += h * a.y;
            tv[o4 * 4 + 2] += h * a.z; tv[o4 * 4 + 3] += h * a.w;
        }
    }
#pragma unroll
    for (int o = 0; o < 32; o++) Vs[t][o] = tv[o];
    __syncthreads();                               // Ks/Vs ready; Wq/Wk/Wv dead
    for (int q = t; q < 1024; q += 128) Wb[0][q] = wo[q];  // overlay Wo

    float m0 = -3e38f, l0 = 0.f, m1 = -3e38f, l1 = 0.f;
    float acc[32];
#pragma unroll
    for (int o = 0; o < 32; o++) acc[o] = 0.f;
    for (int kp = 0; kp < 128; kp++) {
        float s0 = 0.f, s1 = 0.f;
#pragma unroll
        for (int d = 0; d < 16; d++) {
            s0 += qv[d] * Ks[kp][d];
            s1 += qv[16 + d] * Ks[kp][16 + d];
        }
        float nm0 = fmaxf(m0, s0), nm1 = fmaxf(m1, s1);
        float cf0 = __expf(m0 - nm0), cf1 = __expf(m1 - nm1);
        float p0 = __expf(s0 - nm0), p1 = __expf(s1 - nm1);
        l0 = l0 * cf0 + p0; l1 = l1 * cf1 + p1;
        m0 = nm0; m1 = nm1;
#pragma unroll
        for (int d = 0; d < 16; d++) {
            acc[d]      = acc[d]      * cf0 + p0 * Vs[kp][d];
            acc[16 + d] = acc[16 + d] * cf1 + p1 * Vs[kp][16 + d];
        }
    }
    float i0 = 1.f / l0, i1 = 1.f / l1;
#pragma unroll
    for (int d = 0; d < 16; d++) { acc[d] *= i0; acc[16 + d] *= i1; }
    __syncthreads();                               // Wo fully visible

    float r[32];
#pragma unroll
    for (int o = 0; o < 32; o++) r[o] = seq[t * 32 + o];   // residual
    for (int c = 0; c < 32; c++) {
        float ov = acc[c];
#pragma unroll
        for (int o4 = 0; o4 < 8; o4++) {
            float4 a = *(const float4*)&Wb[0][c * 32 + o4 * 4];
            r[o4 * 4 + 0] += ov * a.x; r[o4 * 4 + 1] += ov * a.y;
            r[o4 * 4 + 2] += ov * a.z; r[o4 * 4 + 3] += ov * a.w;
        }
    }
    float mu = 0.f;
#pragma unroll
    for (int o = 0; o < 32; o++) mu += r[o];
    mu *= (1.f / 32.f);
    float var = 0.f;
#pragma unroll
    for (int o = 0; o < 32; o++) { float d = r[o] - mu; var += d * d; }
    var *= (1.f / 32.f);
    float rs = rsqrtf(var + 1e-5f);
#pragma unroll
    for (int o = 0; o < 32; o++) r[o] = (r[o] - mu) * rs * gs[o] + bs2[o];

    if (finalOut == nullptr) {
#pragma unroll
        for (int o4 = 0; o4 < 8; o4++)
            *(float4*)&seq[t * 32 + o4 * 4] =
                make_float4(r[o4 * 4], r[o4 * 4 + 1], r[o4 * 4 + 2], r[o4 * 4 + 3]);
    } else {
        int n = blockIdx.x >> 2, b = blockIdx.x & 3;   // seq chunk = n*B + b
        float* dst = finalOut + ((b * T_ + t) * N_ + n) * D_;
#pragma unroll
        for (int o4 = 0; o4 < 8; o4++)
            *(float4*)&dst[o4 * 4] =
                make_float4(r[o4 * 4], r[o4 * 4 + 1], r[o4 * 4 + 2], r[o4 * 4 + 3]);
    }
}

// ---------------- launcher ---------------------------------------------------
extern "C" void kernel_launch(void* const* d_in, const int* in_sizes, int n_in,
                              void* d_out, int out_size) {
    (void)in_sizes; (void)n_in; (void)out_size;
    const float* x   = (const float*)d_in[0];
    const float* E   = (const float*)d_in[2];
    const float* adj = (const float*)d_in[3];
    const float* gw  = (const float*)d_in[4];
    const float* gb  = (const float*)d_in[5];
    const float* tw1 = (const float*)d_in[6];
    const float* tb1 = (const float*)d_in[7];
    const float* tw2 = (const float*)d_in[8];
    const float* tb2 = (const float*)d_in[9];
    const float* awq = (const float*)d_in[10];
    const float* awk = (const float*)d_in[11];
    const float* awv = (const float*)d_in[12];
    const float* awo = (const float*)d_in[13];
    const float* ag  = (const float*)d_in[14];
    const float* ab  = (const float*)d_in[15];
    float* out = (float*)d_out;

    k_transpose<<<dim3(N_, 8), 256>>>(x);
    k_s2<<<dim3(16, 16), 256>>>(adj);
    k_wn<<<dim3(N_, 3), 256>>>(E, gw, gb);

    // GCN layer 0: in buf0 -> out buf1; layer 1: buf1 -> buf0; layer 2: buf0 -> buf1
    k_agg<<<dim3(128, 8), 256>>>(adj, 0);
    k_combine<<<dim3(N_, 8), 256>>>(0, 0);
    k_agg<<<dim3(128, 8), 256>>>(adj, 1);
    k_combine<<<dim3(N_, 8), 256>>>(1, 1);
    k_agg<<<dim3(128, 8), 256>>>(adj, 0);
    k_combine<<<dim3(N_, 8), 256>>>(0, 2);

    // TCN in-place on buf1
    k_tcn<<<N_ * B_, 128>>>(tw1, tb1, tw2, tb2, 1);

    // attention layers (in-place on buf1; last writes transposed final output)
    k_attn<<<N_ * B_, 128>>>(awq, awk, awv, awo, ag, ab, 1, nullptr);
    k_attn<<<N_ * B_, 128>>>(awq + 1024, awk + 1024, awv + 1024, awo + 1024,
                             ag + 32, ab + 32, 1, out);
}

// round 3
// speedup vs baseline: 1.1548x; 1.1548x over previous
#include <cuda_runtime.h>

#define B_ 4
#define T_ 128
#define N_ 512
#define D_ 32
#define JN_ 16384       // (B*T)*D
#define EMB_ 10

typedef unsigned long long u64;

// ---------------- f32x2 packed helpers (sm_103a FFMA2) -----------------------
__device__ __forceinline__ u64 pack2(float lo, float hi) {
    u64 r; asm("mov.b64 %0, {%1, %2};" : "=l"(r) : "f"(lo), "f"(hi)); return r;
}
__device__ __forceinline__ void unpack2(u64 v, float& lo, float& hi) {
    asm("mov.b64 {%0, %1}, %2;" : "=f"(lo), "=f"(hi) : "l"(v));
}
__device__ __forceinline__ u64 fma2(u64 a, u64 b, u64 c) {
    u64 d; asm("fma.rn.f32x2 %0, %1, %2, %3;" : "=l"(d) : "l"(a), "l"(b), "l"(c)); return d;
}
__device__ __forceinline__ u64 mul2(u64 a, u64 b) {
    u64 d; asm("mul.rn.f32x2 %0, %1, %2;" : "=l"(d) : "l"(a), "l"(b)); return d;
}
__device__ __forceinline__ u64 add2(u64 a, u64 b) {
    u64 d; asm("add.rn.f32x2 %0, %1, %2;" : "=l"(d) : "l"(a), "l"(b)); return d;
}
__device__ __forceinline__ u64 relu2(u64 v) {
    float a, b; unpack2(v, a, b);
    return pack2(fmaxf(a, 0.f), fmaxf(b, 0.f));
}

// ---------------- scratch (device globals; no allocations allowed) ----------
__device__ float g_buf0[N_ * JN_];       // layout (n, bt, c), bt = b*T+t
__device__ float g_buf1[N_ * JN_];
__device__ float g_xg[2 * N_ * JN_];     // aggregated supports k=1,2
__device__ float g_S2[N_ * N_];
__device__ float g_W[3 * N_ * 3 * D_ * D_];   // per-layer per-node (k,c,o)
__device__ float g_bias[3 * N_ * D_];

// ---------------- transpose x (bt,n,c) -> (n,bt,c) --------------------------
__global__ void k_transpose(const float* __restrict__ x) {
    int n = blockIdx.x, bt0 = blockIdx.y * 64, tid = threadIdx.x;
#pragma unroll
    for (int j = 0; j < 8; j++) {
        int idx = j * 256 + tid;
        int r = idx >> 5, c = idx & 31;
        g_buf0[n * JN_ + (bt0 + r) * D_ + c] =
            x[(bt0 + r) * (N_ * D_) + n * D_ + c];
    }
}

// ---------------- S2 = 2*adj@adj - I ----------------------------------------
__global__ void k_s2(const float* __restrict__ A) {
    __shared__ float As[32][33], Bs[32][33];
    int by = blockIdx.y, bx = blockIdx.x, tid = threadIdx.x;
    int ty = tid >> 5, tx = tid & 31;
    float acc[4] = {0.f, 0.f, 0.f, 0.f};
    for (int m0 = 0; m0 < N_; m0 += 32) {
#pragma unroll
        for (int i = 0; i < 4; i++) {
            int r = ty + i * 8;
            As[r][tx] = A[(by * 32 + r) * N_ + m0 + tx];
            Bs[r][tx] = A[(m0 + r) * N_ + bx * 32 + tx];
        }
        __syncthreads();
#pragma unroll
        for (int m = 0; m < 32; m++) {
            float b = Bs[m][tx];
#pragma unroll
            for (int i = 0; i < 4; i++) acc[i] += As[ty + i * 8][m] * b;
        }
        __syncthreads();
    }
#pragma unroll
    for (int i = 0; i < 4; i++) {
        int r = by * 32 + ty + i * 8, c = bx * 32 + tx;
        g_S2[r * N_ + c] = 2.f * acc[i] - (r == c ? 1.f : 0.f);
    }
}

// ---------------- per-node GCN weights: W[n,k,c,o] = sum_e E[n,e] gw[e,k,c,o]
__global__ void k_wn(const float* __restrict__ E, const float* __restrict__ gw,
                     const float* __restrict__ gb) {
    int n = blockIdx.x, L = blockIdx.y, tid = threadIdx.x;
    float Er[EMB_];
#pragma unroll
    for (int e = 0; e < EMB_; e++) Er[e] = E[n * EMB_ + e];
    const float* g0 = gw + L * (EMB_ * 3072);
    float* wout = g_W + (L * N_ + n) * 3072;
    for (int idx = tid; idx < 3072; idx += 256) {
        float a = 0.f;
#pragma unroll
        for (int e = 0; e < EMB_; e++) a += Er[e] * g0[e * 3072 + idx];
        wout[idx] = a;
    }
    if (tid < 32) {
        const float* b0 = gb + L * (EMB_ * 32);
        float a = 0.f;
#pragma unroll
        for (int e = 0; e < EMB_; e++) a += Er[e] * b0[e * 32 + tid];
        g_bias[(L * N_ + n) * 32 + tid] = a;
    }
}

// ---------------- aggregation GEMM: [adj;S2](1024x512) @ H(512x16384) -------
// register-prefetch double buffering: gmem load of tile m+1 overlaps compute m
__global__ void k_agg(const float* __restrict__ adj, int inSel) {
    __shared__ float As[16][132];
    __shared__ float Bs[16][132];
    const float* Hin = inSel ? g_buf1 : g_buf0;
    int bx = blockIdx.x, by = blockIdx.y, tid = threadIdx.x;
    const float* Ap = (by < 4) ? (adj + by * 128 * N_) : (g_S2 + (by - 4) * 128 * N_);
    int bn0 = bx * 128;
    int ty = tid >> 4, tx = tid & 15;
    float acc[8][8];
#pragma unroll
    for (int i = 0; i < 8; i++)
#pragma unroll
        for (int j = 0; j < 8; j++) acc[i][j] = 0.f;

    // thread's fixed load slots (q = tid, tid+256)
    int qa0r = tid >> 2,        qa0c = (tid & 3) * 4;
    int qa1r = (tid + 256) >> 2, qa1c = ((tid + 256) & 3) * 4;
    int qb0k = tid >> 5,        qb0c = (tid & 31) * 4;
    int qb1k = (tid + 256) >> 5, qb1c = ((tid + 256) & 31) * 4;

    float4 pa0, pa1, pb0, pb1;
    pa0 = *(const float4*)&Ap[qa0r * N_ + 0 + qa0c];
    pa1 = *(const float4*)&Ap[qa1r * N_ + 0 + qa1c];
    pb0 = *(const float4*)&Hin[(0 + qb0k) * JN_ + bn0 + qb0c];
    pb1 = *(const float4*)&Hin[(0 + qb1k) * JN_ + bn0 + qb1c];

    for (int m0 = 0; m0 < N_; m0 += 16) {
        // store staged tile to smem (A transposed)
        As[qa0c + 0][qa0r] = pa0.x; As[qa0c + 1][qa0r] = pa0.y;
        As[qa0c + 2][qa0r] = pa0.z; As[qa0c + 3][qa0r] = pa0.w;
        As[qa1c + 0][qa1r] = pa1.x; As[qa1c + 1][qa1r] = pa1.y;
        As[qa1c + 2][qa1r] = pa1.z; As[qa1c + 3][qa1r] = pa1.w;
        *(float4*)&Bs[qb0k][qb0c] = pb0;
        *(float4*)&Bs[qb1k][qb1c] = pb1;
        __syncthreads();
        if (m0 + 16 < N_) {
            int m1 = m0 + 16;
            pa0 = *(const float4*)&Ap[qa0r * N_ + m1 + qa0c];
            pa1 = *(const float4*)&Ap[qa1r * N_ + m1 + qa1c];
            pb0 = *(const float4*)&Hin[(m1 + qb0k) * JN_ + bn0 + qb0c];
            pb1 = *(const float4*)&Hin[(m1 + qb1k) * JN_ + bn0 + qb1c];
        }
#pragma unroll
        for (int kk = 0; kk < 16; kk++) {
            float ra[8], rb[8];
            *(float4*)&ra[0] = *(const float4*)&As[kk][ty * 8];
            *(float4*)&ra[4] = *(const float4*)&As[kk][ty * 8 + 4];
            *(float4*)&rb[0] = *(const float4*)&Bs[kk][tx * 8];
            *(float4*)&rb[4] = *(const float4*)&Bs[kk][tx * 8 + 4];
#pragma unroll
            for (int i = 0; i < 8; i++)
#pragma unroll
                for (int j = 0; j < 8; j++) acc[i][j] += ra[i] * rb[j];
        }
        __syncthreads();
    }
    int r0 = by * 128 + ty * 8;
#pragma unroll
    for (int i = 0; i < 8; i++) {
        float* o = &g_xg[(r0 + i) * JN_ + bn0 + tx * 8];
        *(float4*)&o[0] = make_float4(acc[i][0], acc[i][1], acc[i][2], acc[i][3]);
        *(float4*)&o[4] = make_float4(acc[i][4], acc[i][5], acc[i][6], acc[i][7]);
    }
}

// ---------------- combine: out[n,bt,o] = sum_kc [H|xg1|xg2] * W[n] + b[n] ---
// transposed smem X, 4bt x 4o register tile, 128 threads
__global__ void k_combine(int inSel, int L) {
    __shared__ float Xin[96][68];
    __shared__ float Ws[3072];
    __shared__ float bs[32];
    const float* Hin = inSel ? g_buf1 : g_buf0;
    float* Hout = inSel ? g_buf0 : g_buf1;
    int n = blockIdx.x, bt0 = blockIdx.y * 64, tid = threadIdx.x;
    const float* Wl = g_W + (L * N_ + n) * 3072;
    for (int q = tid; q < 3072; q += 128) Ws[q] = Wl[q];
    if (tid < 32) bs[tid] = g_bias[(L * N_ + n) * 32 + tid];
    const float* s0 = Hin + n * JN_ + bt0 * D_;
    const float* s1 = g_xg + n * JN_ + bt0 * D_;
    const float* s2 = g_xg + (N_ + n) * JN_ + bt0 * D_;
#pragma unroll
    for (int q = tid; q < 2048; q += 128) {
        int r = q >> 5, c = q & 31;
        Xin[c][r] = s0[q];
        Xin[32 + c][r] = s1[q];
        Xin[64 + c][r] = s2[q];
    }
    __syncthreads();
    int to = tid & 7, tb = tid >> 3;  // o4 = to*4, bt4 = tb*4
    float acc[4][4];
#pragma unroll
    for (int i = 0; i < 4; i++)
#pragma unroll
        for (int j = 0; j < 4; j++) acc[i][j] = 0.f;
    for (int kc = 0; kc < 96; kc++) {
        float4 xv = *(const float4*)&Xin[kc][tb * 4];
        float4 wv = *(const float4*)&Ws[kc * 32 + to * 4];
        acc[0][0] += xv.x * wv.x; acc[0][1] += xv.x * wv.y;
        acc[0][2] += xv.x * wv.z; acc[0][3] += xv.x * wv.w;
        acc[1][0] += xv.y * wv.x; acc[1][1] += xv.y * wv.y;
        acc[1][2] += xv.y * wv.z; acc[1][3] += xv.y * wv.w;
        acc[2][0] += xv.z * wv.x; acc[2][1] += xv.z * wv.y;
        acc[2][2] += xv.z * wv.z; acc[2][3] += xv.z * wv.w;
        acc[3][0] += xv.w * wv.x; acc[3][1] += xv.w * wv.y;
        acc[3][2] += xv.w * wv.z; acc[3][3] += xv.w * wv.w;
    }
    float4 bv = *(const float4*)&bs[to * 4];
#pragma unroll
    for (int i = 0; i < 4; i++) {
        int bt = bt0 + tb * 4 + i;
        *(float4*)&Hout[n * JN_ + bt * D_ + to * 4] =
            make_float4(acc[i][0] + bv.x, acc[i][1] + bv.y,
                        acc[i][2] + bv.z, acc[i][3] + bv.w);
    }
}

// ---------------- fused TCN: f32x2-packed, 2 sequences per block ------------
// dynamic smem: e01(16KB) wd2(8KB) bb(256B) y0(33KB) y1(33KB) = 90880 B
#define TCN_SMEM 90880
__global__ void __launch_bounds__(128)
k_tcn(const float* __restrict__ w1, const float* __restrict__ b1,
      const float* __restrict__ w2, const float* __restrict__ b2, int sel) {
    extern __shared__ char dsm[];
    ulonglong2* e01 = (ulonglong2*)dsm;                 // [1024] {dup w0, dup w1}
    u64* wd2 = (u64*)(dsm + 16384);                     // [1024] dup w2
    u64* bb  = (u64*)(dsm + 16384 + 8192);              // [32] dup bias
    u64 (*y0)[129] = (u64(*)[129])(dsm + 24832);        // [32][129] packed pair
    u64 (*y1)[129] = (u64(*)[129])(dsm + 24832 + 33024);

    float* base = sel ? g_buf1 : g_buf0;
    float* seqA = base + (2 * blockIdx.x) * 4096;
    float* seqB = seqA + 4096;
    int t = threadIdx.x;

#pragma unroll
    for (int j = 0; j < 32; j++) {
        int idx = j * 128 + t;
        int c = idx & 31, tt = idx >> 5;
        y0[c][tt] = pack2(seqA[idx], seqB[idx]);
    }
    for (int blk = 0; blk < 3; blk++) {
        int dil = 1 << blk;
        __syncthreads();   // y0 ready; previous weight readers done
        const float* ws = w1 + blk * 3072;
        for (int q = t; q < 1024; q += 128) {
            float a = ws[q * 3], b = ws[q * 3 + 1], c = ws[q * 3 + 2];
            e01[q] = make_ulonglong2(pack2(a, a), pack2(b, b));
            wd2[q] = pack2(c, c);
        }
        if (t < 32) { float v = b1[blk * 32 + t]; bb[t] = pack2(v, v); }
        __syncthreads();
        u64 acc[32];
#pragma unroll
        for (int o = 0; o < 32; o++) acc[o] = bb[o];
        for (int c = 0; c < 32; c++) {
            u64 i0 = (t >= 2 * dil) ? y0[c][t - 2 * dil] : 0ULL;
            u64 i1 = (t >= dil) ? y0[c][t - dil] : 0ULL;
            u64 i2 = y0[c][t];
#pragma unroll
            for (int o = 0; o < 32; o++) {
                ulonglong2 w01 = e01[o * 32 + c];
                acc[o] = fma2(w01.x, i0, acc[o]);
                acc[o] = fma2(w01.y, i1, acc[o]);
                acc[o] = fma2(wd2[o * 32 + c], i2, acc[o]);
            }
        }
#pragma unroll
        for (int o = 0; o < 32; o++) y1[o][t] = relu2(acc[o]);
        __syncthreads();   // y1 visible; conv1 weights dead
        const float* ws2 = w2 + blk * 3072;
        for (int q = t; q < 1024; q += 128) {
            float a = ws2[q * 3], b = ws2[q * 3 + 1], c = ws2[q * 3 + 2];
            e01[q] = make_ulonglong2(pack2(a, a), pack2(b, b));
            wd2[q] = pack2(c, c);
        }
        if (t < 32) { float v = b2[blk * 32 + t]; bb[t] = pack2(v, v); }
        __syncthreads();
#pragma unroll
        for (int o = 0; o < 32; o++) acc[o] = bb[o];
        for (int c = 0; c < 32; c++) {
            u64 i0 = (t >= 2 * dil) ? y1[c][t - 2 * dil] : 0ULL;
            u64 i1 = (t >= dil) ? y1[c][t - dil] : 0ULL;
            u64 i2 = y1[c][t];
#pragma unroll
            for (int o = 0; o < 32; o++) {
                ulonglong2 w01 = e01[o * 32 + c];
                acc[o] = fma2(w01.x, i0, acc[o]);
                acc[o] = fma2(w01.y, i1, acc[o]);
                acc[o] = fma2(wd2[o * 32 + c], i2, acc[o]);
            }
        }
        // residual + relu; thread touches only its own column t of y0
#pragma unroll
        for (int o = 0; o < 32; o++)
            y0[o][t] = relu2(add2(relu2(acc[o]), y0[o][t]));
    }
    __syncthreads();
#pragma unroll
    for (int j = 0; j < 32; j++) {
        int idx = j * 128 + t;
        int c = idx & 31, tt = idx >> 5;
        float lo, hi; unpack2(y0[c][tt], lo, hi);
        seqA[idx] = lo; seqB[idx] = hi;
    }
}

// ---------------- temporal attention + layernorm, f32x2 head-packed ---------
__global__ void __launch_bounds__(128)
k_attn(const float* __restrict__ wq, const float* __restrict__ wk,
       const float* __restrict__ wv, const float* __restrict__ wo,
       const float* __restrict__ gga, const float* __restrict__ bba,
       int sel, float* __restrict__ finalOut) {
    __shared__ ulonglong2 Kp[128][8];   // (K[t][d], K[t][d+16]) pairs
    __shared__ ulonglong2 Vp[128][8];
    __shared__ ulonglong2 Wq2[32][8];   // (W[c][d], W[c][d+16]); reused for Wo
    __shared__ ulonglong2 Wk2[32][8];
    __shared__ ulonglong2 Wv2[32][8];
    __shared__ float gs[32], bs2[32];
    float* seq = (sel ? g_buf1 : g_buf0) + blockIdx.x * 4096;
    int t = threadIdx.x;

    u64* Wq2u = (u64*)Wq2; u64* Wk2u = (u64*)Wk2; u64* Wv2u = (u64*)Wv2;
    for (int idx = t; idx < 512; idx += 128) {
        int c = idx >> 4, d = idx & 15;
        Wq2u[c * 16 + d] = pack2(wq[c * 32 + d], wq[c * 32 + d + 16]);
        Wk2u[c * 16 + d] = pack2(wk[c * 32 + d], wk[c * 32 + d + 16]);
        Wv2u[c * 16 + d] = pack2(wv[c * 32 + d], wv[c * 32 + d + 16]);
    }
    if (t < 32) { gs[t] = gga[t]; bs2[t] = bba[t]; }
    __syncthreads();

    float hrow[32];
#pragma unroll
    for (int o4 = 0; o4 < 8; o4++)
        *(float4*)&hrow[o4 * 4] = *(const float4*)&seq[t * 32 + o4 * 4];

    u64 qp[16], tv[16];
#pragma unroll
    for (int d = 0; d < 16; d++) qp[d] = 0ULL;
    for (int c = 0; c < 32; c++) {
        u64 hd = pack2(hrow[c], hrow[c]);
#pragma unroll
        for (int j = 0; j < 8; j++) {
            ulonglong2 w = Wq2[c][j];
            qp[2 * j] = fma2(w.x, hd, qp[2 * j]);
            qp[2 * j + 1] = fma2(w.y, hd, qp[2 * j + 1]);
        }
    }
    u64 qsc = pack2(0.25f, 0.25f);   // 1/sqrt(16)
#pragma unroll
    for (int d = 0; d < 16; d++) qp[d] = mul2(qp[d], qsc);

#pragma unroll
    for (int d = 0; d < 16; d++) tv[d] = 0ULL;
    for (int c = 0; c < 32; c++) {
        u64 hd = pack2(hrow[c], hrow[c]);
#pragma unroll
        for (int j = 0; j < 8; j++) {
            ulonglong2 w = Wk2[c][j];
            tv[2 * j] = fma2(w.x, hd, tv[2 * j]);
            tv[2 * j + 1] = fma2(w.y, hd, tv[2 * j + 1]);
        }
    }
#pragma unroll
    for (int j = 0; j < 8; j++) Kp[t][j] = make_ulonglong2(tv[2 * j], tv[2 * j + 1]);

#pragma unroll
    for (int d = 0; d < 16; d++) tv[d] = 0ULL;
    for (int c = 0; c < 32; c++) {
        u64 hd = pack2(hrow[c], hrow[c]);
#pragma unroll
        for (int j = 0; j < 8; j++) {
            ulonglong2 w = Wv2[c][j];
            tv[2 * j] = fma2(w.x, hd, tv[2 * j]);
            tv[2 * j + 1] = fma2(w.y, hd, tv[2 * j + 1]);
        }
    }
#pragma unroll
    for (int j = 0; j < 8; j++) Vp[t][j] = make_ulonglong2(tv[2 * j], tv[2 * j + 1]);
    __syncthreads();                    // Kp/Vp ready; Wq dead from here
    for (int idx = t; idx < 512; idx += 128) {
        int c = idx >> 4, d = idx & 15;
        Wq2u[c * 16 + d] = pack2(wo[c * 32 + d], wo[c * 32 + d + 16]);  // overlay Wo
    }

    float m0 = -3e38f, l0 = 0.f, m1 = -3e38f, l1 = 0.f;
    u64 acc[16];
#pragma unroll
    for (int d = 0; d < 16; d++) acc[d] = 0ULL;
    for (int kp = 0; kp < 128; kp++) {
        u64 s = 0ULL;
#pragma unroll
        for (int j = 0; j < 8; j++) {
            ulonglong2 k2 = Kp[kp][j];
            s = fma2(qp[2 * j], k2.x, s);
            s = fma2(qp[2 * j + 1], k2.y, s);
        }
        float s0, s1; unpack2(s, s0, s1);
        float nm0 = fmaxf(m0, s0), nm1 = fmaxf(m1, s1);
        float cf0 = __expf(m0 - nm0), cf1 = __expf(m1 - nm1);
        float p0 = __expf(s0 - nm0), p1 = __expf(s1 - nm1);
        l0 = l0 * cf0 + p0; l1 = l1 * cf1 + p1;
        m0 = nm0; m1 = nm1;
        u64 cfp = pack2(cf0, cf1), pp = pack2(p0, p1);
#pragma unroll
        for (int j = 0; j < 8; j++) {
            ulonglong2 v2 = Vp[kp][j];
            acc[2 * j] = fma2(acc[2 * j], cfp, mul2(pp, v2.x));
            acc[2 * j + 1] = fma2(acc[2 * j + 1], cfp, mul2(pp, v2.y));
        }
    }
    u64 inv = pack2(1.f / l0, 1.f / l1);
    float ov[32];
#pragma unroll
    for (int d = 0; d < 16; d++) {
        u64 a = mul2(acc[d], inv);
        unpack2(a, ov[d], ov[d + 16]);
    }
    __syncthreads();                    // Wo overlay fully visible

    u64 rp[16];
#pragma unroll
    for (int d = 0; d < 16; d++)
        rp[d] = pack2(seq[t * 32 + d], seq[t * 32 + d + 16]);   // residual
    for (int c = 0; c < 32; c++) {
        u64 od = pack2(ov[c], ov[c]);
#pragma unroll
        for (int j = 0; j < 8; j++) {
            ulonglong2 w = Wq2[c][j];    // Wo
            rp[2 * j] = fma2(w.x, od, rp[2 * j]);
            rp[2 * j + 1] = fma2(w.y, od, rp[2 * j + 1]);
        }
    }
    float r[32];
#pragma unroll
    for (int d = 0; d < 16; d++) unpack2(rp[d], r[d], r[d + 16]);
    float mu = 0.f;
#pragma unroll
    for (int o = 0; o < 32; o++) mu += r[o];
    mu *= (1.f / 32.f);
    float var = 0.f;
#pragma unroll
    for (int o = 0; o < 32; o++) { float d = r[o] - mu; var += d * d; }
    var *= (1.f / 32.f);
    float rs = rsqrtf(var + 1e-5f);
#pragma unroll
    for (int o = 0; o < 32; o++) r[o] = (r[o] - mu) * rs * gs[o] + bs2[o];

    if (finalOut == nullptr) {
#pragma unroll
        for (int o4 = 0; o4 < 8; o4++)
            *(float4*)&seq[t * 32 + o4 * 4] =
                make_float4(r[o4 * 4], r[o4 * 4 + 1], r[o4 * 4 + 2], r[o4 * 4 + 3]);
    } else {
        int n = blockIdx.x >> 2, b = blockIdx.x & 3;   // seq chunk = n*B + b
        float* dst = finalOut + ((b * T_ + t) * N_ + n) * D_;
#pragma unroll
        for (int o4 = 0; o4 < 8; o4++)
            *(float4*)&dst[o4 * 4] =
                make_float4(r[o4 * 4], r[o4 * 4 + 1], r[o4 * 4 + 2], r[o4 * 4 + 3]);
    }
}

// ---------------- launcher ---------------------------------------------------
extern "C" void kernel_launch(void* const* d_in, const int* in_sizes, int n_in,
                              void* d_out, int out_size) {
    (void)in_sizes; (void)n_in; (void)out_size;
    const float* x   = (const float*)d_in[0];
    const float* E   = (const float*)d_in[2];
    const float* adj = (const float*)d_in[3];
    const float* gw  = (const float*)d_in[4];
    const float* gb  = (const float*)d_in[5];
    const float* tw1 = (const float*)d_in[6];
    const float* tb1 = (const float*)d_in[7];
    const float* tw2 = (const float*)d_in[8];
    const float* tb2 = (const float*)d_in[9];
    const float* awq = (const float*)d_in[10];
    const float* awk = (const float*)d_in[11];
    const float* awv = (const float*)d_in[12];
    const float* awo = (const float*)d_in[13];
    const float* ag  = (const float*)d_in[14];
    const float* ab  = (const float*)d_in[15];
    float* out = (float*)d_out;

    cudaFuncSetAttribute(k_tcn, cudaFuncAttributeMaxDynamicSharedMemorySize,
                         TCN_SMEM);

    k_transpose<<<dim3(N_, 8), 256>>>(x);
    k_s2<<<dim3(16, 16), 256>>>(adj);
    k_wn<<<dim3(N_, 3), 256>>>(E, gw, gb);

    // GCN layer 0: buf0 -> buf1; layer 1: buf1 -> buf0; layer 2: buf0 -> buf1
    k_agg<<<dim3(128, 8), 256>>>(adj, 0);
    k_combine<<<dim3(N_, 8), 128>>>(0, 0);
    k_agg<<<dim3(128, 8), 256>>>(adj, 1);
    k_combine<<<dim3(N_, 8), 128>>>(1, 1);
    k_agg<<<dim3(128, 8), 256>>>(adj, 0);
    k_combine<<<dim3(N_, 8), 128>>>(0, 2);

    // TCN in-place on buf1, 2 sequences per block
    k_tcn<<<N_ * B_ / 2, 128, TCN_SMEM>>>(tw1, tb1, tw2, tb2, 1);

    // attention layers (in-place on buf1; last writes transposed final output)
    k_attn<<<N_ * B_, 128>>>(awq, awk, awv, awo, ag, ab, 1, nullptr);
    k_attn<<<N_ * B_, 128>>>(awq + 1024, awk + 1024, awv + 1024, awo + 1024,
                             ag + 32, ab + 32, 1, out);
}